// round 6
// baseline (speedup 1.0000x reference)
#include <cuda_runtime.h>
#include <cstdint>
#include <cstddef>

// Problem dims
#define B_ 2
#define M_ 384
#define N_ 96
#define D_ 512
#define J_ 640
#define C_ 1024
#define MN_ (M_*N_)        // 36864
#define RTOT_ (B_*MN_)     // 73728

// Join tiling: BM=128 x BN=128 x BK=32, 256 threads, 8 warps (4m x 2n), warp 32x64
#define BM 128
#define BN 128
#define BK 32
#define NKT (J_/BK)        // 20
#define THREADS 256

// packed h layout: [ks][c][row][pair p], addr in 8B units = ks*532 + c*132 + row
#define H_C2   132                      // 8B units per c step (132 % 16 == 4)
#define H_KS2  (4*H_C2 + 4)             // 532 ; 532 % 16 == 4
#define HS_BYTES (4*H_KS2*8)            // 17024

// packed w smem: [ks*4+c][col][pair], addr8 = (ks*4+c)*W_P2 + col
#define W_P2   132                      // 132 % 16 == 4
#define WS_BYTES (16*W_P2*8)            // 16896

// smem byte offsets
#define SM_AOFF  0
#define SM_TOFF  512
#define SM_HS    1024
#define SM_WS    (SM_HS + 2*HS_BYTES)   // 35072
#define SMEM_TOTAL (SM_WS + 2*WS_BYTES) // 68864  (x2 CTAs = 137.7KB/SM)

// Scratch (device globals)
__device__ float g_a[B_*M_*J_];
__device__ float g_t[B_*N_*J_];
// packed+rounded w_join: word index ((r*C_)+col)*2 + p,
// r = kt*16+ks*4+c, value = tf32(w_join[kt*32+ks*8+c+4p][col])
__device__ unsigned g_wp[(size_t)J_*C_];

// ---------------------------------------------------------------------------
// helpers
// ---------------------------------------------------------------------------
__device__ __forceinline__ uint32_t smem_u32(const void* p) {
    uint32_t a;
    asm("{ .reg .u64 t; cvta.to.shared.u64 t, %1; cvt.u32.u64 %0, t; }"
        : "=r"(a) : "l"(p));
    return a;
}
__device__ __forceinline__ unsigned f2tf32(float x) {
    unsigned r;
    asm("cvt.rna.tf32.f32 %0, %1;" : "=r"(r) : "f"(x));
    return r;
}
__device__ __forceinline__ float fast_tanh(float x) {
    float r;
    asm("tanh.approx.f32 %0, %1;" : "=f"(r) : "f"(x));
    return r;
}
__device__ __forceinline__ void mma_tf32(float d[4],
                                         unsigned a0, unsigned a1, unsigned a2, unsigned a3,
                                         unsigned b0, unsigned b1) {
    asm volatile(
        "mma.sync.aligned.m16n8k8.row.col.f32.tf32.tf32.f32 "
        "{%0,%1,%2,%3}, {%4,%5,%6,%7}, {%8,%9}, {%0,%1,%2,%3};"
        : "+f"(d[0]), "+f"(d[1]), "+f"(d[2]), "+f"(d[3])
        : "r"(a0), "r"(a1), "r"(a2), "r"(a3), "r"(b0), "r"(b1));
}
__device__ __forceinline__ void cp_async16(uint32_t dst, const void* src) {
    asm volatile("cp.async.ca.shared.global [%0], [%1], 16;" :: "r"(dst), "l"(src));
}
#define CP_COMMIT() asm volatile("cp.async.commit_group;" ::: "memory")
#define CP_WAIT0()  asm volatile("cp.async.wait_group 0;" ::: "memory")

// ---------------------------------------------------------------------------
// w_join -> tf32-rounded, k-pair-packed copy
// thread: one (r, colblk of 8). r = kt*16+ks*4+c -> rows j0=kt*32+ks*8+c, j0+4
// ---------------------------------------------------------------------------
__global__ __launch_bounds__(256) void wpack_kernel(const float* __restrict__ wj) {
    int gid   = blockIdx.x * 256 + threadIdx.x;   // 0 .. 320*128-1
    int r     = gid >> 7;                          // 0..319
    int col   = (gid & 127) * 8;
    int kt    = r >> 4;
    int ks    = (r >> 2) & 3;
    int c     = r & 3;
    int j0    = kt * 32 + ks * 8 + c;

    const float* s0 = wj + (size_t)j0 * C_ + col;
    const float* s1 = wj + (size_t)(j0 + 4) * C_ + col;
    unsigned* dst = g_wp + ((size_t)r * C_ + col) * 2;

#pragma unroll
    for (int q = 0; q < 2; ++q) {
        float4 lo = *(const float4*)(s0 + q * 4);
        float4 hi = *(const float4*)(s1 + q * 4);
        uint4 o0, o1;
        o0.x = f2tf32(lo.x); o0.y = f2tf32(hi.x);
        o0.z = f2tf32(lo.y); o0.w = f2tf32(hi.y);
        o1.x = f2tf32(lo.z); o1.y = f2tf32(hi.z);
        o1.z = f2tf32(lo.w); o1.w = f2tf32(hi.w);
        *(uint4*)(dst + q * 8)     = o0;
        *(uint4*)(dst + q * 8 + 4) = o1;
    }
}

// ---------------------------------------------------------------------------
// Projection: out[rows,J] = x[rows,D] @ w[D,J] + bias. 4 rows/block, J split 2.
// ---------------------------------------------------------------------------
__global__ __launch_bounds__(320) void proj_kernel(
    const float* __restrict__ x, const float* __restrict__ w,
    const float* __restrict__ bias, int which)
{
    __shared__ float xs[4][D_];
    float* outp = which ? g_t : g_a;
    const int r0 = blockIdx.x * 4;
    const int j  = blockIdx.y * 320 + threadIdx.x;

    for (int i = threadIdx.x; i < 4 * D_; i += 320)
        xs[i >> 9][i & (D_ - 1)] = x[(r0 + (i >> 9)) * D_ + (i & (D_ - 1))];
    __syncthreads();

    float a0 = 0.f, a1 = 0.f, a2 = 0.f, a3 = 0.f;
#pragma unroll 8
    for (int k = 0; k < D_; ++k) {
        float wv = w[(size_t)k * J_ + j];
        a0 += xs[0][k] * wv; a1 += xs[1][k] * wv;
        a2 += xs[2][k] * wv; a3 += xs[3][k] * wv;
    }
    float bb = bias[j];
    outp[(r0 + 0) * J_ + j] = a0 + bb;
    outp[(r0 + 1) * J_ + j] = a1 + bb;
    outp[(r0 + 2) * J_ + j] = a2 + bb;
    outp[(r0 + 3) * J_ + j] = a3 + bb;
}

// ---------------------------------------------------------------------------
// Fused join GEMM. 256 threads, 8 warps (4m x 2n), warp tile 32x64, 2 CTAs/SM.
// ---------------------------------------------------------------------------
__global__ __launch_bounds__(THREADS, 2) void join_kernel(
    const float* __restrict__ bj, float* __restrict__ out)
{
    extern __shared__ char sm[];
    const uint32_t sb = smem_u32(sm);
    const int tid  = threadIdx.x;
    const int wid  = tid >> 5;
    const int lane = tid & 31;
    const int col0 = blockIdx.x * BN;
    const int row0 = blockIdx.y * BM;

    int* aoffS = (int*)(sm + SM_AOFF);
    int* toffS = (int*)(sm + SM_TOFF);
    if (tid < BM) {
        int gr  = row0 + tid;
        int b   = gr / MN_;
        int rem = gr - b * MN_;
        int m   = rem / N_;
        int n   = rem - m * N_;
        aoffS[tid] = (b * M_ + m) * J_;
        toffS[tid] = (b * N_ + n) * J_;
    }
    __syncthreads();

    // fill mapping: 2 threads per row, each covers 16 consecutive k (2 ks blocks)
    const int hrow = tid >> 1;            // 0..127
    const int kq   = tid & 1;             // 0/1 -> k offset 16*kq, ks blocks 2kq,2kq+1
    const int aoff = aoffS[hrow];
    const int toff = toffS[hrow];

    // warp compute mapping
    const int wm = wid & 3;               // 4 m sub-tiles of 32 rows
    const int wn = wid >> 2;              // 2 n sub-tiles of 64 cols
    const int g  = lane >> 2;
    const int c  = lane & 3;

    float acc[2][8][4];
#pragma unroll
    for (int mi = 0; mi < 2; ++mi)
#pragma unroll
        for (int ni = 0; ni < 8; ++ni)
#pragma unroll
            for (int q = 0; q < 4; ++q) acc[mi][ni][q] = 0.f;

    // ---------------- prologue: tile 0 ----------------
    {
        float va[16], vt[16];
#pragma unroll
        for (int q = 0; q < 4; ++q) {
            *(float4*)&va[q * 4] = *(const float4*)(g_a + aoff + kq * 16 + q * 4);
            *(float4*)&vt[q * 4] = *(const float4*)(g_t + toff + kq * 16 + q * 4);
        }
        uint32_t wbase = sb + SM_WS;
#pragma unroll
        for (int p = 0; p < 4; ++p) {
            int cid = tid + p * THREADS;            // 0..1023
            int wr  = cid >> 6;                     // 0..15 (= ks*4+c)
            int ch  = cid & 63;                     // 16B chunk
            cp_async16(wbase + wr * (W_P2 * 8) + ch * 16,
                       g_wp + ((size_t)wr * C_ + col0) * 2 + ch * 4);
        }
        CP_COMMIT();

        uint2* hd = (uint2*)(sm + SM_HS);
#pragma unroll
        for (int ksl = 0; ksl < 2; ++ksl)
#pragma unroll
            for (int cc = 0; cc < 4; ++cc) {
                int kl = ksl * 8 + cc;
                uint2 q;
                q.x = f2tf32(fast_tanh(va[kl]     + vt[kl]));
                q.y = f2tf32(fast_tanh(va[kl + 4] + vt[kl + 4]));
                hd[(2 * kq + ksl) * H_KS2 + cc * H_C2 + hrow] = q;
            }
        CP_WAIT0();
        __syncthreads();
    }

    // ---------------- main loop ----------------
    for (int kt = 0; kt < NKT; ++kt) {
        const int buf = kt & 1;
        const int nb  = buf ^ 1;
        const uint2* hsb = (const uint2*)(sm + SM_HS + buf * HS_BYTES);
        const uint2* wsb = (const uint2*)(sm + SM_WS + buf * WS_BYTES);

        float va[16], vt[16];
        if (kt < NKT - 1) {
            const int k0n = (kt + 1) * BK;
#pragma unroll
            for (int q = 0; q < 4; ++q) {
                *(float4*)&va[q * 4] = *(const float4*)(g_a + aoff + k0n + kq * 16 + q * 4);
                *(float4*)&vt[q * 4] = *(const float4*)(g_t + toff + k0n + kq * 16 + q * 4);
            }
            uint32_t wbase = sb + SM_WS + nb * WS_BYTES;
            const size_t wrow0 = (size_t)(kt + 1) * 16;
#pragma unroll
            for (int p = 0; p < 4; ++p) {
                int cid = tid + p * THREADS;
                int wr  = cid >> 6;
                int ch  = cid & 63;
                cp_async16(wbase + wr * (W_P2 * 8) + ch * 16,
                           g_wp + ((wrow0 + wr) * C_ + col0) * 2 + ch * 4);
            }
            CP_COMMIT();
        }

        // compute current tile
#pragma unroll
        for (int ks = 0; ks < BK / 8; ++ks) {
            unsigned a_frag[2][4];
            const int abase = ks * H_KS2 + c * H_C2;
#pragma unroll
            for (int mi = 0; mi < 2; ++mi) {
                int rlo = wm * 32 + mi * 16 + g;
                uint2 u0 = hsb[abase + rlo];
                uint2 u1 = hsb[abase + rlo + 8];
                a_frag[mi][0] = u0.x; a_frag[mi][2] = u0.y;
                a_frag[mi][1] = u1.x; a_frag[mi][3] = u1.y;
            }
            const int bbase = (ks * 4 + c) * W_P2 + wn * 64;
#pragma unroll
            for (int ni = 0; ni < 8; ++ni) {
                uint2 bb = wsb[bbase + ni * 8 + g];
#pragma unroll
                for (int mi = 0; mi < 2; ++mi)
                    mma_tf32(acc[mi][ni],
                             a_frag[mi][0], a_frag[mi][1], a_frag[mi][2], a_frag[mi][3],
                             bb.x, bb.y);
            }
        }

        // finish next h tile
        if (kt < NKT - 1) {
            uint2* hd = (uint2*)(sm + SM_HS + nb * HS_BYTES);
#pragma unroll
            for (int ksl = 0; ksl < 2; ++ksl)
#pragma unroll
                for (int cc = 0; cc < 4; ++cc) {
                    int kl = ksl * 8 + cc;
                    uint2 q;
                    q.x = f2tf32(fast_tanh(va[kl]     + vt[kl]));
                    q.y = f2tf32(fast_tanh(va[kl + 4] + vt[kl + 4]));
                    hd[(2 * kq + ksl) * H_KS2 + cc * H_C2 + hrow] = q;
                }
            CP_WAIT0();
        }
        __syncthreads();
    }

    // ---------------- epilogue ----------------
#pragma unroll
    for (int ni = 0; ni < 8; ++ni) {
        int gcol = col0 + wn * 64 + ni * 8 + c * 2;
        float2 bb = *(const float2*)(bj + gcol);
#pragma unroll
        for (int mi = 0; mi < 2; ++mi) {
            int grow = row0 + wm * 32 + mi * 16 + g;
            float2 v0 = make_float2(acc[mi][ni][0] + bb.x, acc[mi][ni][1] + bb.y);
            float2 v1 = make_float2(acc[mi][ni][2] + bb.x, acc[mi][ni][3] + bb.y);
            *(float2*)(out + (size_t)grow * C_ + gcol)       = v0;
            *(float2*)(out + (size_t)(grow + 8) * C_ + gcol) = v1;
        }
    }
}

// ---------------------------------------------------------------------------
// launch
// ---------------------------------------------------------------------------
extern "C" void kernel_launch(void* const* d_in, const int* in_sizes, int n_in,
                              void* d_out, int out_size)
{
    const float* enc     = (const float*)d_in[0];
    const float* dec     = (const float*)d_in[1];
    const float* w_audio = (const float*)d_in[2];
    const float* b_audio = (const float*)d_in[3];
    const float* w_text  = (const float*)d_in[4];
    const float* b_text  = (const float*)d_in[5];
    const float* w_join  = (const float*)d_in[6];
    const float* b_join  = (const float*)d_in[7];
    float* out = (float*)d_out;

    static int smem_set = 0;
    if (!smem_set) {
        cudaFuncSetAttribute(join_kernel, cudaFuncAttributeMaxDynamicSharedMemorySize,
                             SMEM_TOTAL);
        smem_set = 1;
    }

    wpack_kernel<<<(320 * 128) / 256, 256>>>(w_join);
    proj_kernel<<<dim3((B_ * M_) / 4, 2), 320>>>(enc, w_audio, b_audio, 0);
    proj_kernel<<<dim3((B_ * N_) / 4, 2), 320>>>(dec, w_text, b_text, 1);

    join_kernel<<<dim3(C_ / BN, RTOT_ / BM), THREADS, SMEM_TOTAL>>>(b_join, out);
}

// round 7
// speedup vs baseline: 1.4262x; 1.4262x over previous
#include <cuda_runtime.h>
#include <cuda_fp16.h>
#include <cstdint>
#include <cstddef>

// Problem dims
#define B_ 2
#define M_ 384
#define N_ 96
#define D_ 512
#define J_ 640
#define C_ 1024
#define MN_ (M_*N_)        // 36864
#define RTOT_ (B_*MN_)     // 73728

// Join tiling: BM=128 x BN=256 x BK=32, 512 threads, 16 warps (4m x 4n), warp 32x64
#define BM 128
#define BN 256
#define BK 32
#define NKT (J_/BK)        // 20
#define THREADS 512

// h smem: uint2 at [ks]*HKS + [c]*HC + row ; word0 = h2(k=16ks+2c,+1), word1 = (+8,+9)
#define HC  132            // 132 % 16 == 4  -> conflict-free a LDS.64
#define HKS 536            // 4*HC + 8 ; 2*HKS % 32 == 16 -> conflict-free h STS.32
#define HS_BYTES (2*HKS*8) // 8576
// w smem: uint2 at [ks*4+c]*WC + col ; word0 = h2(k=16ks+2c,+1), word1 = (+8,+9)
#define WC  260            // 260 % 16 == 4 -> conflict-free b LDS.64
#define WS_BYTES (8*WC*8)  // 16640

#define SM_AOFF  0
#define SM_TOFF  512
#define SM_HS    1024
#define SM_WS    (SM_HS + 2*HS_BYTES)   // 18176
#define SMEM_TOTAL (SM_WS + 2*WS_BYTES) // 51456

// Scratch (device globals)
__device__ float g_a[B_*M_*J_];
__device__ float g_t[B_*N_*J_];
// packed fp16 w_join: uint2 g_wph[r*C_+col], r = kt*8+ks*4+c:
//   word0 = h2(wj[kt*32+ks*16+2c][col], wj[..+2c+1][col]), word1 = rows +8,+9
__device__ uint2 g_wph[(size_t)(J_/4)*C_];

// ---------------------------------------------------------------------------
// helpers
// ---------------------------------------------------------------------------
__device__ __forceinline__ uint32_t smem_u32(const void* p) {
    uint32_t a;
    asm("{ .reg .u64 t; cvta.to.shared.u64 t, %1; cvt.u32.u64 %0, t; }"
        : "=r"(a) : "l"(p));
    return a;
}
__device__ __forceinline__ float fast_tanh(float x) {
    float r;
    asm("tanh.approx.f32 %0, %1;" : "=f"(r) : "f"(x));
    return r;
}
// pack two fp32 -> f16x2 register, lo = first arg (low half), hi = second
__device__ __forceinline__ unsigned pack_h2(float lo, float hi) {
    unsigned r;
    asm("cvt.rn.f16x2.f32 %0, %2, %1;" : "=r"(r) : "f"(lo), "f"(hi));
    return r;
}
__device__ __forceinline__ void mma_f16(float d[4],
                                        unsigned a0, unsigned a1, unsigned a2, unsigned a3,
                                        unsigned b0, unsigned b1) {
    asm volatile(
        "mma.sync.aligned.m16n8k16.row.col.f32.f16.f16.f32 "
        "{%0,%1,%2,%3}, {%4,%5,%6,%7}, {%8,%9}, {%0,%1,%2,%3};"
        : "+f"(d[0]), "+f"(d[1]), "+f"(d[2]), "+f"(d[3])
        : "r"(a0), "r"(a1), "r"(a2), "r"(a3), "r"(b0), "r"(b1));
}
__device__ __forceinline__ void cp_async16(uint32_t dst, const void* src) {
    asm volatile("cp.async.ca.shared.global [%0], [%1], 16;" :: "r"(dst), "l"(src));
}
#define CP_COMMIT() asm volatile("cp.async.commit_group;" ::: "memory")
#define CP_WAIT0()  asm volatile("cp.async.wait_group 0;" ::: "memory")

// ---------------------------------------------------------------------------
// w_join -> fp16 packed layout
// ---------------------------------------------------------------------------
__global__ __launch_bounds__(256) void wpack_kernel(const float* __restrict__ wj) {
    int gid = blockIdx.x * 256 + threadIdx.x;     // 0 .. 160*1024-1
    int r   = gid >> 10;                          // 0..159
    int col = gid & 1023;
    int kt  = r >> 3;
    int ks  = (r >> 2) & 1;
    int c   = r & 3;
    int j0  = kt * 32 + ks * 16 + 2 * c;

    uint2 o;
    o.x = pack_h2(wj[(size_t)j0 * C_ + col],       wj[(size_t)(j0 + 1) * C_ + col]);
    o.y = pack_h2(wj[(size_t)(j0 + 8) * C_ + col], wj[(size_t)(j0 + 9) * C_ + col]);
    g_wph[(size_t)r * C_ + col] = o;
}

// ---------------------------------------------------------------------------
// Projection: out[rows,J] = x[rows,D] @ w[D,J] + bias. 16 rows/block, J split 2.
// ---------------------------------------------------------------------------
__global__ __launch_bounds__(320) void proj_kernel(
    const float* __restrict__ x, const float* __restrict__ w,
    const float* __restrict__ bias, int which)
{
    __shared__ float xs[16][D_];
    float* outp = which ? g_t : g_a;
    const int r0 = blockIdx.x * 16;
    const int j  = blockIdx.y * 320 + threadIdx.x;

    for (int i = threadIdx.x; i < 16 * D_; i += 320)
        xs[i >> 9][i & (D_ - 1)] = x[(r0 + (i >> 9)) * D_ + (i & (D_ - 1))];
    __syncthreads();

    float acc[16];
#pragma unroll
    for (int r = 0; r < 16; ++r) acc[r] = 0.f;

#pragma unroll 4
    for (int k = 0; k < D_; ++k) {
        float wv = w[(size_t)k * J_ + j];
#pragma unroll
        for (int r = 0; r < 16; ++r) acc[r] += xs[r][k] * wv;
    }
    float bb = bias[j];
#pragma unroll
    for (int r = 0; r < 16; ++r)
        outp[(r0 + r) * J_ + j] = acc[r] + bb;
}

// ---------------------------------------------------------------------------
// Fused join GEMM, fp16 mma m16n8k16. 512 threads, 16 warps (4m x 4n), warp 32x64.
// ---------------------------------------------------------------------------
__global__ __launch_bounds__(THREADS, 1) void join_kernel(
    const float* __restrict__ bj, float* __restrict__ out)
{
    extern __shared__ char sm[];
    const uint32_t sb = smem_u32(sm);
    const int tid  = threadIdx.x;
    const int wid  = tid >> 5;
    const int lane = tid & 31;
    const int col0 = blockIdx.x * BN;
    const int row0 = blockIdx.y * BM;

    int* aoffS = (int*)(sm + SM_AOFF);
    int* toffS = (int*)(sm + SM_TOFF);
    if (tid < BM) {
        int gr  = row0 + tid;
        int b   = gr / MN_;
        int rem = gr - b * MN_;
        int m   = rem / N_;
        int n   = rem - m * N_;
        aoffS[tid] = (b * M_ + m) * J_;
        toffS[tid] = (b * N_ + n) * J_;
    }
    __syncthreads();

    // fill mapping: 4 threads per row, thread covers 8 consecutive k
    const int hrow = tid >> 2;            // 0..127
    const int kq   = tid & 3;             // k offset = kq*8 ; ks = kq>>1, wsel = kq&1
    const int ksq  = kq >> 1;
    const int wsel = kq & 1;
    const int aoff = aoffS[hrow];
    const int toff = toffS[hrow];

    // warp compute mapping
    const int wm = wid & 3;               // 4 m sub-tiles of 32 rows
    const int wn = wid >> 2;              // 4 n sub-tiles of 64 cols
    const int g  = lane >> 2;
    const int c  = lane & 3;

    float acc[2][8][4];
#pragma unroll
    for (int mi = 0; mi < 2; ++mi)
#pragma unroll
        for (int ni = 0; ni < 8; ++ni)
#pragma unroll
            for (int q = 0; q < 4; ++q) acc[mi][ni][q] = 0.f;

    // ---------------- prologue: tile 0 ----------------
    {
        float va[8], vt[8];
        *(float4*)&va[0] = *(const float4*)(g_a + aoff + kq * 8);
        *(float4*)&va[4] = *(const float4*)(g_a + aoff + kq * 8 + 4);
        *(float4*)&vt[0] = *(const float4*)(g_t + toff + kq * 8);
        *(float4*)&vt[4] = *(const float4*)(g_t + toff + kq * 8 + 4);

        uint32_t wbase = sb + SM_WS;
#pragma unroll
        for (int p = 0; p < 2; ++p) {
            int cid = tid + p * THREADS;         // 0..1023
            int r   = cid >> 7;                  // 0..7
            int ch  = cid & 127;                 // 16B chunk (2 cols)
            cp_async16(wbase + (r * WC + ch * 2) * 8,
                       g_wph + (size_t)r * C_ + col0 + ch * 2);
        }
        CP_COMMIT();

        unsigned* hd = (unsigned*)(sm + SM_HS);
#pragma unroll
        for (int cc = 0; cc < 4; ++cc) {
            unsigned v = pack_h2(fast_tanh(va[2 * cc]     + vt[2 * cc]),
                                 fast_tanh(va[2 * cc + 1] + vt[2 * cc + 1]));
            hd[2 * (ksq * HKS + cc * HC + hrow) + wsel] = v;
        }
        CP_WAIT0();
        __syncthreads();
    }

    // ---------------- main loop ----------------
    for (int kt = 0; kt < NKT; ++kt) {
        const int buf = kt & 1;
        const int nb  = buf ^ 1;
        const uint2* hsb = (const uint2*)(sm + SM_HS + buf * HS_BYTES);
        const uint2* wsb = (const uint2*)(sm + SM_WS + buf * WS_BYTES);

        float va[8], vt[8];
        if (kt < NKT - 1) {
            const int k0n = (kt + 1) * BK + kq * 8;
            *(float4*)&va[0] = *(const float4*)(g_a + aoff + k0n);
            *(float4*)&va[4] = *(const float4*)(g_a + aoff + k0n + 4);
            *(float4*)&vt[0] = *(const float4*)(g_t + toff + k0n);
            *(float4*)&vt[4] = *(const float4*)(g_t + toff + k0n + 4);

            uint32_t wbase = sb + SM_WS + nb * WS_BYTES;
            const size_t wr0 = (size_t)(kt + 1) * 8;
#pragma unroll
            for (int p = 0; p < 2; ++p) {
                int cid = tid + p * THREADS;
                int r   = cid >> 7;
                int ch  = cid & 127;
                cp_async16(wbase + (r * WC + ch * 2) * 8,
                           g_wph + (wr0 + r) * C_ + col0 + ch * 2);
            }
            CP_COMMIT();
        }

        // compute current tile: 2 k-steps of K=16
#pragma unroll
        for (int ks = 0; ks < 2; ++ks) {
            unsigned a_frag[2][4];
            const int abase = ks * HKS + c * HC;
#pragma unroll
            for (int mi = 0; mi < 2; ++mi) {
                int rlo = wm * 32 + mi * 16 + g;
                uint2 u0 = hsb[abase + rlo];       // a0 (k lo), a2 (k hi)
                uint2 u1 = hsb[abase + rlo + 8];   // a1, a3
                a_frag[mi][0] = u0.x; a_frag[mi][2] = u0.y;
                a_frag[mi][1] = u1.x; a_frag[mi][3] = u1.y;
            }
            const int bbase = (ks * 4 + c) * WC + wn * 64;
#pragma unroll
            for (int ni = 0; ni < 8; ++ni) {
                uint2 bb = wsb[bbase + ni * 8 + g];
#pragma unroll
                for (int mi = 0; mi < 2; ++mi)
                    mma_f16(acc[mi][ni],
                            a_frag[mi][0], a_frag[mi][1], a_frag[mi][2], a_frag[mi][3],
                            bb.x, bb.y);
            }
        }

        // finish next h tile
        if (kt < NKT - 1) {
            unsigned* hd = (unsigned*)(sm + SM_HS + nb * HS_BYTES);
#pragma unroll
            for (int cc = 0; cc < 4; ++cc) {
                unsigned v = pack_h2(fast_tanh(va[2 * cc]     + vt[2 * cc]),
                                     fast_tanh(va[2 * cc + 1] + vt[2 * cc + 1]));
                hd[2 * (ksq * HKS + cc * HC + hrow) + wsel] = v;
            }
            CP_WAIT0();
        }
        __syncthreads();
    }

    // ---------------- epilogue: + b_join, fp32 stores ----------------
#pragma unroll
    for (int ni = 0; ni < 8; ++ni) {
        int gcol = col0 + wn * 64 + ni * 8 + c * 2;
        float2 bb = *(const float2*)(bj + gcol);
#pragma unroll
        for (int mi = 0; mi < 2; ++mi) {
            int grow = row0 + wm * 32 + mi * 16 + g;
            float2 v0 = make_float2(acc[mi][ni][0] + bb.x, acc[mi][ni][1] + bb.y);
            float2 v1 = make_float2(acc[mi][ni][2] + bb.x, acc[mi][ni][3] + bb.y);
            *(float2*)(out + (size_t)grow * C_ + gcol)       = v0;
            *(float2*)(out + (size_t)(grow + 8) * C_ + gcol) = v1;
        }
    }
}

// ---------------------------------------------------------------------------
// launch
// ---------------------------------------------------------------------------
extern "C" void kernel_launch(void* const* d_in, const int* in_sizes, int n_in,
                              void* d_out, int out_size)
{
    const float* enc     = (const float*)d_in[0];
    const float* dec     = (const float*)d_in[1];
    const float* w_audio = (const float*)d_in[2];
    const float* b_audio = (const float*)d_in[3];
    const float* w_text  = (const float*)d_in[4];
    const float* b_text  = (const float*)d_in[5];
    const float* w_join  = (const float*)d_in[6];
    const float* b_join  = (const float*)d_in[7];
    float* out = (float*)d_out;

    static int smem_set = 0;
    if (!smem_set) {
        cudaFuncSetAttribute(join_kernel, cudaFuncAttributeMaxDynamicSharedMemorySize,
                             SMEM_TOTAL);
        smem_set = 1;
    }

    wpack_kernel<<<(160 * 1024) / 256, 256>>>(w_join);
    proj_kernel<<<dim3((B_ * M_) / 16, 2), 320>>>(enc, w_audio, b_audio, 0);
    proj_kernel<<<dim3((B_ * N_) / 16, 2), 320>>>(dec, w_text, b_text, 1);

    join_kernel<<<dim3(C_ / BN, RTOT_ / BM), THREADS, SMEM_TOTAL>>>(b_join, out);
}

// round 8
// speedup vs baseline: 1.5625x; 1.0956x over previous
#include <cuda_runtime.h>
#include <cuda_fp16.h>
#include <cstdint>
#include <cstddef>

// Problem dims
#define B_ 2
#define M_ 384
#define N_ 96
#define D_ 512
#define J_ 640
#define C_ 1024
#define MN_ (M_*N_)        // 36864
#define RTOT_ (B_*MN_)     // 73728

// Join tiling: BM=128 x BN=256 x BK=32, 512 threads, 16 warps (4m x 4n), warp 32x64
#define BM 128
#define BN 256
#define BK 32
#define NKT (J_/BK)        // 20
#define THREADS 512

// fp16 row-major tiles with 80B row stride (banks 20r mod 32 -> ldmatrix conflict-free)
#define ROWB 80
#define HS_B (BM*ROWB)     // 10240
#define WS_B (BN*ROWB)     // 20480

#define SM_AOFF  0
#define SM_TOFF  512
#define SM_HS    1024
#define SM_WS    (SM_HS + 2*HS_B)      // 21504
#define SMEM_TOTAL (SM_WS + 2*WS_B)    // 62464

// Scratch (device globals)
__device__ float g_a[B_*M_*J_];
__device__ float g_t[B_*N_*J_];
__device__ __half g_wh[(size_t)C_*J_];   // w_join transposed [col][j], fp16

// ---------------------------------------------------------------------------
// helpers
// ---------------------------------------------------------------------------
__device__ __forceinline__ uint32_t smem_u32(const void* p) {
    uint32_t a;
    asm("{ .reg .u64 t; cvta.to.shared.u64 t, %1; cvt.u32.u64 %0, t; }"
        : "=r"(a) : "l"(p));
    return a;
}
__device__ __forceinline__ float fast_tanh(float x) {
    float r;
    asm("tanh.approx.f32 %0, %1;" : "=f"(r) : "f"(x));
    return r;
}
// pack two fp32 -> f16x2 (first arg = low half)
__device__ __forceinline__ unsigned pack_h2(float lo, float hi) {
    unsigned r;
    asm("cvt.rn.f16x2.f32 %0, %2, %1;" : "=r"(r) : "f"(lo), "f"(hi));
    return r;
}
__device__ __forceinline__ void mma_f16(float d[4],
                                        unsigned a0, unsigned a1, unsigned a2, unsigned a3,
                                        unsigned b0, unsigned b1) {
    asm volatile(
        "mma.sync.aligned.m16n8k16.row.col.f32.f16.f16.f32 "
        "{%0,%1,%2,%3}, {%4,%5,%6,%7}, {%8,%9}, {%0,%1,%2,%3};"
        : "+f"(d[0]), "+f"(d[1]), "+f"(d[2]), "+f"(d[3])
        : "r"(a0), "r"(a1), "r"(a2), "r"(a3), "r"(b0), "r"(b1));
}
__device__ __forceinline__ void ldm_x4(unsigned r[4], uint32_t addr) {
    asm volatile("ldmatrix.sync.aligned.m8n8.x4.shared.b16 {%0,%1,%2,%3}, [%4];"
        : "=r"(r[0]), "=r"(r[1]), "=r"(r[2]), "=r"(r[3]) : "r"(addr));
}
__device__ __forceinline__ void cp_async16(uint32_t dst, const void* src) {
    asm volatile("cp.async.ca.shared.global [%0], [%1], 16;" :: "r"(dst), "l"(src));
}
#define CP_COMMIT() asm volatile("cp.async.commit_group;" ::: "memory")
#define CP_WAIT0()  asm volatile("cp.async.wait_group 0;" ::: "memory")

// ---------------------------------------------------------------------------
// w_join [J,C] fp32 -> g_wh [C,J] fp16 (transpose via smem tile)
// ---------------------------------------------------------------------------
__global__ __launch_bounds__(256) void wpack_kernel(const float* __restrict__ wj) {
    __shared__ float t[32][33];
    const int c0 = blockIdx.x * 32, j0 = blockIdx.y * 32;
    const int tx = threadIdx.x & 31, ty = threadIdx.x >> 5;
#pragma unroll
    for (int i = 0; i < 4; ++i)
        t[ty + i * 8][tx] = wj[(size_t)(j0 + ty + i * 8) * C_ + c0 + tx];
    __syncthreads();
#pragma unroll
    for (int i = 0; i < 4; ++i)
        g_wh[(size_t)(c0 + ty + i * 8) * J_ + j0 + tx] = __float2half(t[tx][ty + i * 8]);
}

// ---------------------------------------------------------------------------
// Projection: out[rows,J] = x[rows,D] @ w[D,J] + bias. 16 rows/block, J split 2.
// ---------------------------------------------------------------------------
__global__ __launch_bounds__(320) void proj_kernel(
    const float* __restrict__ x, const float* __restrict__ w,
    const float* __restrict__ bias, int which)
{
    __shared__ float xs[16][D_];
    float* outp = which ? g_t : g_a;
    const int r0 = blockIdx.x * 16;
    const int j  = blockIdx.y * 320 + threadIdx.x;

    for (int i = threadIdx.x; i < 16 * D_; i += 320)
        xs[i >> 9][i & (D_ - 1)] = x[(r0 + (i >> 9)) * D_ + (i & (D_ - 1))];
    __syncthreads();

    float acc[16];
#pragma unroll
    for (int r = 0; r < 16; ++r) acc[r] = 0.f;

#pragma unroll 4
    for (int k = 0; k < D_; ++k) {
        float wv = w[(size_t)k * J_ + j];
#pragma unroll
        for (int r = 0; r < 16; ++r) acc[r] += xs[r][k] * wv;
    }
    float bb = bias[j];
#pragma unroll
    for (int r = 0; r < 16; ++r)
        outp[(r0 + r) * J_ + j] = acc[r] + bb;
}

// ---------------------------------------------------------------------------
// Fused join GEMM, fp16 mma m16n8k16 + ldmatrix fragments.
// ---------------------------------------------------------------------------
__global__ __launch_bounds__(THREADS, 1) void join_kernel(
    const float* __restrict__ bj, float* __restrict__ out)
{
    extern __shared__ char sm[];
    const uint32_t sb = smem_u32(sm);
    const int tid  = threadIdx.x;
    const int wid  = tid >> 5;
    const int lane = tid & 31;
    const int col0 = blockIdx.x * BN;
    const int row0 = blockIdx.y * BM;

    int* aoffS = (int*)(sm + SM_AOFF);
    int* toffS = (int*)(sm + SM_TOFF);
    if (tid < BM) {
        int gr  = row0 + tid;
        int b   = gr / MN_;
        int rem = gr - b * MN_;
        int m   = rem / N_;
        int n   = rem - m * N_;
        aoffS[tid] = (b * M_ + m) * J_;
        toffS[tid] = (b * N_ + n) * J_;
    }
    __syncthreads();

    // fill mapping: 4 threads per row, each an 8-k chunk (one STS.128)
    const int hrow = tid >> 2;
    const int kq   = tid & 3;
    const int aoff = aoffS[hrow];
    const int toff = toffS[hrow];

    // warp compute mapping
    const int wm = wid & 3;
    const int wn = wid >> 2;
    const int g  = lane >> 2;
    const int c  = lane & 3;

    // ldmatrix lane base offsets (bytes within tile)
    const int l7 = lane & 7;
    const int lm = lane >> 3;           // matrix index 0..3
    // A: matrices (rows0-7 klo)(rows8-15 klo)(rows0-7 khi)(rows8-15 khi)
    const uint32_t a_loc = (uint32_t)((wm * 32 + (lm & 1) * 8 + l7) * ROWB + (lm >> 1) * 16);
    // B: matrices (nblk0 klo)(nblk0 khi)(nblk1 klo)(nblk1 khi), nblk p*16(+8)
    const uint32_t b_loc = (uint32_t)((wn * 64 + (lm >> 1) * 8 + l7) * ROWB + (lm & 1) * 16);

    float acc[2][8][4];
#pragma unroll
    for (int mi = 0; mi < 2; ++mi)
#pragma unroll
        for (int ni = 0; ni < 8; ++ni)
#pragma unroll
            for (int q = 0; q < 4; ++q) acc[mi][ni][q] = 0.f;

    // ---------------- prologue: tile 0 ----------------
    {
        float va[8], vt[8];
        *(float4*)&va[0] = *(const float4*)(g_a + aoff + kq * 8);
        *(float4*)&va[4] = *(const float4*)(g_a + aoff + kq * 8 + 4);
        *(float4*)&vt[0] = *(const float4*)(g_t + toff + kq * 8);
        *(float4*)&vt[4] = *(const float4*)(g_t + toff + kq * 8 + 4);

        uint32_t wbase = sb + SM_WS;
#pragma unroll
        for (int p = 0; p < 2; ++p) {
            int cid = tid + p * THREADS;         // 0..1023
            int cc  = cid >> 2;
            int kk  = cid & 3;
            cp_async16(wbase + cc * ROWB + kk * 16,
                       (const char*)g_wh + ((size_t)(col0 + cc) * J_) * 2 + kk * 16);
        }
        CP_COMMIT();

        uint4 q;
        q.x = pack_h2(fast_tanh(va[0] + vt[0]), fast_tanh(va[1] + vt[1]));
        q.y = pack_h2(fast_tanh(va[2] + vt[2]), fast_tanh(va[3] + vt[3]));
        q.z = pack_h2(fast_tanh(va[4] + vt[4]), fast_tanh(va[5] + vt[5]));
        q.w = pack_h2(fast_tanh(va[6] + vt[6]), fast_tanh(va[7] + vt[7]));
        *(uint4*)(sm + SM_HS + hrow * ROWB + kq * 16) = q;

        CP_WAIT0();
        __syncthreads();
    }

    // ---------------- main loop ----------------
    for (int kt = 0; kt < NKT; ++kt) {
        const int buf = kt & 1;
        const int nb  = buf ^ 1;
        const uint32_t ha = sb + SM_HS + buf * HS_B + a_loc;
        const uint32_t hb = sb + SM_WS + buf * WS_B + b_loc;

        float va[8], vt[8];
        if (kt < NKT - 1) {
            const int k0n = (kt + 1) * BK + kq * 8;
            *(float4*)&va[0] = *(const float4*)(g_a + aoff + k0n);
            *(float4*)&va[4] = *(const float4*)(g_a + aoff + k0n + 4);
            *(float4*)&vt[0] = *(const float4*)(g_t + toff + k0n);
            *(float4*)&vt[4] = *(const float4*)(g_t + toff + k0n + 4);

            uint32_t wbase = sb + SM_WS + nb * WS_B;
            const size_t ksrc = (size_t)(kt + 1) * BK * 2;   // byte offset in row
#pragma unroll
            for (int p = 0; p < 2; ++p) {
                int cid = tid + p * THREADS;
                int cc  = cid >> 2;
                int kk  = cid & 3;
                cp_async16(wbase + cc * ROWB + kk * 16,
                           (const char*)g_wh + ((size_t)(col0 + cc) * J_) * 2 + ksrc + kk * 16);
            }
            CP_COMMIT();
        }

        // compute: 2 k-steps of K=16
#pragma unroll
        for (int ks = 0; ks < 2; ++ks) {
            unsigned af[2][4];
            ldm_x4(af[0], ha + ks * 32);
            ldm_x4(af[1], ha + 1280 + ks * 32);          // +16 rows * 80B
            unsigned bf[4][4];
#pragma unroll
            for (int p = 0; p < 4; ++p)
                ldm_x4(bf[p], hb + p * 1280 + ks * 32);  // +16 cols * 80B per p
#pragma unroll
            for (int p = 0; p < 4; ++p) {
#pragma unroll
                for (int mi = 0; mi < 2; ++mi) {
                    mma_f16(acc[mi][2 * p],
                            af[mi][0], af[mi][1], af[mi][2], af[mi][3],
                            bf[p][0], bf[p][1]);
                    mma_f16(acc[mi][2 * p + 1],
                            af[mi][0], af[mi][1], af[mi][2], af[mi][3],
                            bf[p][2], bf[p][3]);
                }
            }
        }

        // finish next h tile
        if (kt < NKT - 1) {
            uint4 q;
            q.x = pack_h2(fast_tanh(va[0] + vt[0]), fast_tanh(va[1] + vt[1]));
            q.y = pack_h2(fast_tanh(va[2] + vt[2]), fast_tanh(va[3] + vt[3]));
            q.z = pack_h2(fast_tanh(va[4] + vt[4]), fast_tanh(va[5] + vt[5]));
            q.w = pack_h2(fast_tanh(va[6] + vt[6]), fast_tanh(va[7] + vt[7]));
            *(uint4*)(sm + SM_HS + nb * HS_B + hrow * ROWB + kq * 16) = q;
            CP_WAIT0();
        }
        __syncthreads();
    }

    // ---------------- epilogue: + b_join, fp32 stores ----------------
#pragma unroll
    for (int ni = 0; ni < 8; ++ni) {
        int gcol = col0 + wn * 64 + ni * 8 + c * 2;
        float2 bb = *(const float2*)(bj + gcol);
#pragma unroll
        for (int mi = 0; mi < 2; ++mi) {
            int grow = row0 + wm * 32 + mi * 16 + g;
            float2 v0 = make_float2(acc[mi][ni][0] + bb.x, acc[mi][ni][1] + bb.y);
            float2 v1 = make_float2(acc[mi][ni][2] + bb.x, acc[mi][ni][3] + bb.y);
            *(float2*)(out + (size_t)grow * C_ + gcol)       = v0;
            *(float2*)(out + (size_t)(grow + 8) * C_ + gcol) = v1;
        }
    }
}

// ---------------------------------------------------------------------------
// launch
// ---------------------------------------------------------------------------
extern "C" void kernel_launch(void* const* d_in, const int* in_sizes, int n_in,
                              void* d_out, int out_size)
{
    const float* enc     = (const float*)d_in[0];
    const float* dec     = (const float*)d_in[1];
    const float* w_audio = (const float*)d_in[2];
    const float* b_audio = (const float*)d_in[3];
    const float* w_text  = (const float*)d_in[4];
    const float* b_text  = (const float*)d_in[5];
    const float* w_join  = (const float*)d_in[6];
    const float* b_join  = (const float*)d_in[7];
    float* out = (float*)d_out;

    static int smem_set = 0;
    if (!smem_set) {
        cudaFuncSetAttribute(join_kernel, cudaFuncAttributeMaxDynamicSharedMemorySize,
                             SMEM_TOTAL);
        smem_set = 1;
    }

    wpack_kernel<<<dim3(C_ / 32, J_ / 32), 256>>>(w_join);
    proj_kernel<<<dim3((B_ * M_) / 16, 2), 320>>>(enc, w_audio, b_audio, 0);
    proj_kernel<<<dim3((B_ * N_) / 16, 2), 320>>>(dec, w_text, b_text, 1);

    join_kernel<<<dim3(C_ / BN, RTOT_ / BM), THREADS, SMEM_TOTAL>>>(b_join, out);
}

// round 9
// speedup vs baseline: 1.6972x; 1.0862x over previous
#include <cuda_runtime.h>
#include <cuda_fp16.h>
#include <cstdint>
#include <cstddef>

// Problem dims
#define B_ 2
#define M_ 384
#define N_ 96
#define D_ 512
#define J_ 640
#define C_ 1024
#define MN_ (M_*N_)        // 36864
#define RTOT_ (B_*MN_)     // 73728

// Join tiling: BM=128 x BN=256 x BK=64, 512 threads, 16 warps (4m x 4n), warp 32x64
#define BM 128
#define BN 256
#define BK 64
#define NKT (J_/BK)        // 10
#define THREADS 512

// fp16 row-major tiles, 144B row stride (banks 4r mod 32 -> ldmatrix/STS conflict-free)
#define ROWB 144
#define HS_B (BM*ROWB)     // 18432
#define WS_B (BN*ROWB)     // 36864

#define SM_AOFF  0
#define SM_TOFF  512
#define SM_HS    1024
#define SM_WS    (SM_HS + 2*HS_B)      // 37888
#define SMEM_TOTAL (SM_WS + 2*WS_B)    // 111616

// Scratch (device globals)
__device__ __half g_ah[B_*M_*J_];        // audio proj + bias, fp16
__device__ __half g_th[B_*N_*J_];        // text proj + bias, fp16
__device__ __half g_wh[(size_t)C_*J_];   // w_join transposed [col][j], fp16

// ---------------------------------------------------------------------------
// helpers
// ---------------------------------------------------------------------------
__device__ __forceinline__ uint32_t smem_u32(const void* p) {
    uint32_t a;
    asm("{ .reg .u64 t; cvta.to.shared.u64 t, %1; cvt.u32.u64 %0, t; }"
        : "=r"(a) : "l"(p));
    return a;
}
__device__ __forceinline__ float fast_tanh(float x) {
    float r;
    asm("tanh.approx.f32 %0, %1;" : "=f"(r) : "f"(x));
    return r;
}
__device__ __forceinline__ unsigned pack_h2(float lo, float hi) {
    unsigned r;
    asm("cvt.rn.f16x2.f32 %0, %2, %1;" : "=r"(r) : "f"(lo), "f"(hi));
    return r;
}
__device__ __forceinline__ void mma_f16(float d[4],
                                        unsigned a0, unsigned a1, unsigned a2, unsigned a3,
                                        unsigned b0, unsigned b1) {
    asm volatile(
        "mma.sync.aligned.m16n8k16.row.col.f32.f16.f16.f32 "
        "{%0,%1,%2,%3}, {%4,%5,%6,%7}, {%8,%9}, {%0,%1,%2,%3};"
        : "+f"(d[0]), "+f"(d[1]), "+f"(d[2]), "+f"(d[3])
        : "r"(a0), "r"(a1), "r"(a2), "r"(a3), "r"(b0), "r"(b1));
}
__device__ __forceinline__ void ldm_x4(unsigned r[4], uint32_t addr) {
    asm volatile("ldmatrix.sync.aligned.m8n8.x4.shared.b16 {%0,%1,%2,%3}, [%4];"
        : "=r"(r[0]), "=r"(r[1]), "=r"(r[2]), "=r"(r[3]) : "r"(addr));
}
__device__ __forceinline__ void cp_async16(uint32_t dst, const void* src) {
    asm volatile("cp.async.ca.shared.global [%0], [%1], 16;" :: "r"(dst), "l"(src));
}
#define CP_COMMIT() asm volatile("cp.async.commit_group;" ::: "memory")
#define CP_WAIT0()  asm volatile("cp.async.wait_group 0;" ::: "memory")

// combine 4 half2 (a) + 4 half2 (t) -> tanh -> packed uint4
__device__ __forceinline__ uint4 h_combine(uint4 a, uint4 t) {
    uint4 q;
    unsigned* av = (unsigned*)&a;
    unsigned* tv = (unsigned*)&t;
    unsigned* qv = (unsigned*)&q;
#pragma unroll
    for (int i = 0; i < 4; ++i) {
        float2 af = __half22float2(*(__half2*)&av[i]);
        float2 tf = __half22float2(*(__half2*)&tv[i]);
        qv[i] = pack_h2(fast_tanh(af.x + tf.x), fast_tanh(af.y + tf.y));
    }
    return q;
}

// ---------------------------------------------------------------------------
// w_join [J,C] fp32 -> g_wh [C,J] fp16 (transpose via smem tile)
// ---------------------------------------------------------------------------
__global__ __launch_bounds__(256) void wpack_kernel(const float* __restrict__ wj) {
    __shared__ float t[32][33];
    const int c0 = blockIdx.x * 32, j0 = blockIdx.y * 32;
    const int tx = threadIdx.x & 31, ty = threadIdx.x >> 5;
#pragma unroll
    for (int i = 0; i < 4; ++i)
        t[ty + i * 8][tx] = wj[(size_t)(j0 + ty + i * 8) * C_ + c0 + tx];
    __syncthreads();
#pragma unroll
    for (int i = 0; i < 4; ++i)
        g_wh[(size_t)(c0 + ty + i * 8) * J_ + j0 + tx] = __float2half(t[tx][ty + i * 8]);
}

// ---------------------------------------------------------------------------
// Projection: out[rows,J] = x[rows,D] @ w[D,J] + bias -> fp16.
// 128 threads: 8 rows x 128 cols per block; thread = rows {rw, rw+4} x 4 cols.
// ---------------------------------------------------------------------------
__global__ __launch_bounds__(128) void proj_kernel(
    const float* __restrict__ x, const float* __restrict__ w,
    const float* __restrict__ bias, int which)
{
    __shared__ float xs[8][D_];
    const int r0 = blockIdx.x * 8;
    const int j  = blockIdx.y * 128 + (threadIdx.x & 31) * 4;
    const int rw = threadIdx.x >> 5;           // 0..3 -> rows rw, rw+4

    // load 8 rows of x (contiguous) as float4
    for (int i = threadIdx.x; i < 8 * D_ / 4; i += 128)
        ((float4*)xs)[i] = ((const float4*)x)[(size_t)r0 * (D_ / 4) + i];
    __syncthreads();

    float4 a0 = make_float4(0.f, 0.f, 0.f, 0.f);
    float4 a1 = make_float4(0.f, 0.f, 0.f, 0.f);
#pragma unroll 4
    for (int k = 0; k < D_; ++k) {
        float4 wv = *(const float4*)&w[(size_t)k * J_ + j];
        float x0 = xs[rw][k], x1 = xs[rw + 4][k];
        a0.x += x0 * wv.x; a0.y += x0 * wv.y; a0.z += x0 * wv.z; a0.w += x0 * wv.w;
        a1.x += x1 * wv.x; a1.y += x1 * wv.y; a1.z += x1 * wv.z; a1.w += x1 * wv.w;
    }
    float4 bb = *(const float4*)&bias[j];
    __half* outp = which ? g_th : g_ah;
    uint2 o0, o1;
    o0.x = pack_h2(a0.x + bb.x, a0.y + bb.y);
    o0.y = pack_h2(a0.z + bb.z, a0.w + bb.w);
    o1.x = pack_h2(a1.x + bb.x, a1.y + bb.y);
    o1.y = pack_h2(a1.z + bb.z, a1.w + bb.w);
    *(uint2*)&outp[(size_t)(r0 + rw) * J_ + j]     = o0;
    *(uint2*)&outp[(size_t)(r0 + rw + 4) * J_ + j] = o1;
}

// ---------------------------------------------------------------------------
// Fused join GEMM, fp16 mma m16n8k16 + ldmatrix, BK=64.
// ---------------------------------------------------------------------------
__global__ __launch_bounds__(THREADS, 1) void join_kernel(
    const float* __restrict__ bj, float* __restrict__ out)
{
    extern __shared__ char sm[];
    const uint32_t sb = smem_u32(sm);
    const int tid  = threadIdx.x;
    const int wid  = tid >> 5;
    const int lane = tid & 31;
    const int col0 = blockIdx.x * BN;
    const int row0 = blockIdx.y * BM;

    int* aoffS = (int*)(sm + SM_AOFF);
    int* toffS = (int*)(sm + SM_TOFF);
    if (tid < BM) {
        int gr  = row0 + tid;
        int b   = gr / MN_;
        int rem = gr - b * MN_;
        int m   = rem / N_;
        int n   = rem - m * N_;
        aoffS[tid] = (b * M_ + m) * J_;
        toffS[tid] = (b * N_ + n) * J_;
    }
    __syncthreads();

    // fill mapping: 4 threads per row, each a 16-k chunk (2x LDG.128, 2x STS.128)
    const int hrow = tid >> 2;
    const int kq   = tid & 3;               // k chunk = kq*16
    const int aoff = aoffS[hrow] + kq * 16;
    const int toff = toffS[hrow] + kq * 16;

    // warp compute mapping
    const int wm = wid & 3;
    const int wn = wid >> 2;
    const int g  = lane >> 2;
    const int c  = lane & 3;

    // ldmatrix lane base offsets
    const int l7 = lane & 7;
    const int lm = lane >> 3;
    const uint32_t a_loc = (uint32_t)((wm * 32 + (lm & 1) * 8 + l7) * ROWB + (lm >> 1) * 16);
    const uint32_t b_loc = (uint32_t)((wn * 64 + (lm >> 1) * 8 + l7) * ROWB + (lm & 1) * 16);

    float acc[2][8][4];
#pragma unroll
    for (int mi = 0; mi < 2; ++mi)
#pragma unroll
        for (int ni = 0; ni < 8; ++ni)
#pragma unroll
            for (int q = 0; q < 4; ++q) acc[mi][ni][q] = 0.f;

    // ---------------- prologue: tile 0 ----------------
    {
        uint4 va0 = *(const uint4*)(g_ah + aoff);
        uint4 va1 = *(const uint4*)(g_ah + aoff + 8);
        uint4 vt0 = *(const uint4*)(g_th + toff);
        uint4 vt1 = *(const uint4*)(g_th + toff + 8);

        uint32_t wbase = sb + SM_WS;
#pragma unroll
        for (int p = 0; p < 4; ++p) {
            int cid = tid + p * THREADS;         // 0..2047
            int cc  = cid >> 3;                  // col 0..255
            int kk  = cid & 7;                   // 16B chunk
            cp_async16(wbase + cc * ROWB + kk * 16,
                       (const char*)g_wh + (size_t)(col0 + cc) * J_ * 2 + kk * 16);
        }
        CP_COMMIT();

        char* hd = sm + SM_HS + hrow * ROWB + kq * 32;
        *(uint4*)(hd)      = h_combine(va0, vt0);
        *(uint4*)(hd + 16) = h_combine(va1, vt1);

        CP_WAIT0();
        __syncthreads();
    }

    // ---------------- main loop ----------------
    for (int kt = 0; kt < NKT; ++kt) {
        const int buf = kt & 1;
        const int nb  = buf ^ 1;
        const uint32_t ha = sb + SM_HS + buf * HS_B + a_loc;
        const uint32_t hb = sb + SM_WS + buf * WS_B + b_loc;

        uint4 va0, va1, vt0, vt1;
        if (kt < NKT - 1) {
            const int k0n = (kt + 1) * BK;
            va0 = *(const uint4*)(g_ah + aoff + k0n);
            va1 = *(const uint4*)(g_ah + aoff + k0n + 8);
            vt0 = *(const uint4*)(g_th + toff + k0n);
            vt1 = *(const uint4*)(g_th + toff + k0n + 8);

            uint32_t wbase = sb + SM_WS + nb * WS_B;
            const size_t ksrc = (size_t)(kt + 1) * BK * 2;   // byte offset in w row
#pragma unroll
            for (int p = 0; p < 4; ++p) {
                int cid = tid + p * THREADS;
                int cc  = cid >> 3;
                int kk  = cid & 7;
                cp_async16(wbase + cc * ROWB + kk * 16,
                           (const char*)g_wh + (size_t)(col0 + cc) * J_ * 2 + ksrc + kk * 16);
            }
            CP_COMMIT();
        }

        // compute: 4 k-steps of K=16
#pragma unroll
        for (int ks = 0; ks < 4; ++ks) {
            unsigned af[2][4];
            ldm_x4(af[0], ha + ks * 32);
            ldm_x4(af[1], ha + 16 * ROWB + ks * 32);
            unsigned bf[4][4];
#pragma unroll
            for (int p = 0; p < 4; ++p)
                ldm_x4(bf[p], hb + p * (16 * ROWB) + ks * 32);
#pragma unroll
            for (int p = 0; p < 4; ++p) {
#pragma unroll
                for (int mi = 0; mi < 2; ++mi) {
                    mma_f16(acc[mi][2 * p],
                            af[mi][0], af[mi][1], af[mi][2], af[mi][3],
                            bf[p][0], bf[p][1]);
                    mma_f16(acc[mi][2 * p + 1],
                            af[mi][0], af[mi][1], af[mi][2], af[mi][3],
                            bf[p][2], bf[p][3]);
                }
            }
        }

        // finish next h tile
        if (kt < NKT - 1) {
            char* hd = sm + SM_HS + nb * HS_B + hrow * ROWB + kq * 32;
            *(uint4*)(hd)      = h_combine(va0, vt0);
            *(uint4*)(hd + 16) = h_combine(va1, vt1);
            CP_WAIT0();
        }
        __syncthreads();
    }

    // ---------------- epilogue: + b_join, fp32 stores ----------------
#pragma unroll
    for (int ni = 0; ni < 8; ++ni) {
        int gcol = col0 + wn * 64 + ni * 8 + c * 2;
        float2 bb = *(const float2*)(bj + gcol);
#pragma unroll
        for (int mi = 0; mi < 2; ++mi) {
            int grow = row0 + wm * 32 + mi * 16 + g;
            float2 v0 = make_float2(acc[mi][ni][0] + bb.x, acc[mi][ni][1] + bb.y);
            float2 v1 = make_float2(acc[mi][ni][2] + bb.x, acc[mi][ni][3] + bb.y);
            *(float2*)(out + (size_t)grow * C_ + gcol)       = v0;
            *(float2*)(out + (size_t)(grow + 8) * C_ + gcol) = v1;
        }
    }
}

// ---------------------------------------------------------------------------
// launch
// ---------------------------------------------------------------------------
extern "C" void kernel_launch(void* const* d_in, const int* in_sizes, int n_in,
                              void* d_out, int out_size)
{
    const float* enc     = (const float*)d_in[0];
    const float* dec     = (const float*)d_in[1];
    const float* w_audio = (const float*)d_in[2];
    const float* b_audio = (const float*)d_in[3];
    const float* w_text  = (const float*)d_in[4];
    const float* b_text  = (const float*)d_in[5];
    const float* w_join  = (const float*)d_in[6];
    const float* b_join  = (const float*)d_in[7];
    float* out = (float*)d_out;

    static int smem_set = 0;
    if (!smem_set) {
        cudaFuncSetAttribute(join_kernel, cudaFuncAttributeMaxDynamicSharedMemorySize,
                             SMEM_TOTAL);
        smem_set = 1;
    }

    wpack_kernel<<<dim3(C_ / 32, J_ / 32), 256>>>(w_join);
    proj_kernel<<<dim3((B_ * M_) / 8, J_ / 128), 128>>>(enc, w_audio, b_audio, 0);
    proj_kernel<<<dim3((B_ * N_) / 8, J_ / 128), 128>>>(dec, w_text, b_text, 1);

    join_kernel<<<dim3(C_ / BN, RTOT_ / BM), THREADS, SMEM_TOTAL>>>(b_join, out);
}

// round 10
// speedup vs baseline: 2.2118x; 1.3032x over previous
#include <cuda_runtime.h>
#include <cuda_fp16.h>
#include <cstdint>
#include <cstddef>

// Problem dims
#define B_ 2
#define M_ 384
#define N_ 96
#define D_ 512
#define J_ 640
#define C_ 1024
#define MN_ (M_*N_)        // 36864
#define RTOT_ (B_*MN_)     // 73728

// Join tiling: BM=128 x BN=256 x BK=64, 512 threads, 16 warps (4m x 4n), warp 32x64
#define BM 128
#define BN 256
#define BK 64
#define NKT (J_/BK)        // 10
#define THREADS 512

// fp16 row-major tiles, 144B row stride (banks 4r mod 32 -> ldmatrix/STS conflict-free)
#define ROWB 144
#define HS_B (BM*ROWB)     // 18432
#define WS_B (BN*ROWB)     // 36864

#define SM_AOFF  0
#define SM_TOFF  512
#define SM_HS    1024
#define SM_WS    (SM_HS + 2*HS_B)      // 37888
#define SMEM_TOTAL (SM_WS + 2*WS_B)    // 111616

// prep grid split
#define NB_WPACK ((C_/32)*(J_/32))     // 640
#define NB_ENC   ((B_*M_/4)*(J_/128))  // 192*5 = 960
#define NB_DEC   ((B_*N_/4)*(J_/128))  // 48*5  = 240
#define NB_PREP  (NB_WPACK + NB_ENC + NB_DEC)  // 1840

// Scratch (device globals)
__device__ __half g_ah[B_*M_*J_];        // audio proj + bias, fp16
__device__ __half g_th[B_*N_*J_];        // text proj + bias, fp16
__device__ __half g_wh[(size_t)C_*J_];   // w_join transposed [col][j], fp16

// ---------------------------------------------------------------------------
// helpers
// ---------------------------------------------------------------------------
__device__ __forceinline__ uint32_t smem_u32(const void* p) {
    uint32_t a;
    asm("{ .reg .u64 t; cvta.to.shared.u64 t, %1; cvt.u32.u64 %0, t; }"
        : "=r"(a) : "l"(p));
    return a;
}
__device__ __forceinline__ float fast_tanh(float x) {
    float r;
    asm("tanh.approx.f32 %0, %1;" : "=f"(r) : "f"(x));
    return r;
}
__device__ __forceinline__ unsigned pack_h2(float lo, float hi) {
    unsigned r;
    asm("cvt.rn.f16x2.f32 %0, %2, %1;" : "=r"(r) : "f"(lo), "f"(hi));
    return r;
}
__device__ __forceinline__ void mma_f16(float d[4],
                                        unsigned a0, unsigned a1, unsigned a2, unsigned a3,
                                        unsigned b0, unsigned b1) {
    asm volatile(
        "mma.sync.aligned.m16n8k16.row.col.f32.f16.f16.f32 "
        "{%0,%1,%2,%3}, {%4,%5,%6,%7}, {%8,%9}, {%0,%1,%2,%3};"
        : "+f"(d[0]), "+f"(d[1]), "+f"(d[2]), "+f"(d[3])
        : "r"(a0), "r"(a1), "r"(a2), "r"(a3), "r"(b0), "r"(b1));
}
__device__ __forceinline__ void ldm_x4(unsigned r[4], uint32_t addr) {
    asm volatile("ldmatrix.sync.aligned.m8n8.x4.shared.b16 {%0,%1,%2,%3}, [%4];"
        : "=r"(r[0]), "=r"(r[1]), "=r"(r[2]), "=r"(r[3]) : "r"(addr));
}
__device__ __forceinline__ void cp_async16(uint32_t dst, const void* src) {
    asm volatile("cp.async.ca.shared.global [%0], [%1], 16;" :: "r"(dst), "l"(src));
}
#define CP_COMMIT() asm volatile("cp.async.commit_group;" ::: "memory")
#define CP_WAIT0()  asm volatile("cp.async.wait_group 0;" ::: "memory")

// combine 4 half2 (a) + 4 half2 (t) -> tanh -> packed uint4
__device__ __forceinline__ uint4 h_combine(uint4 a, uint4 t) {
    uint4 q;
    unsigned* av = (unsigned*)&a;
    unsigned* tv = (unsigned*)&t;
    unsigned* qv = (unsigned*)&q;
#pragma unroll
    for (int i = 0; i < 4; ++i) {
        float2 af = __half22float2(*(__half2*)&av[i]);
        float2 tf = __half22float2(*(__half2*)&tv[i]);
        qv[i] = pack_h2(fast_tanh(af.x + tf.x), fast_tanh(af.y + tf.y));
    }
    return q;
}

// ---------------------------------------------------------------------------
// Fused prep kernel: one launch does
//   [0, 640)      w_join [J,C] -> g_wh [C,J] fp16 transpose (32x32 tiles)
//   [640, 1600)   enc projection  (4 rows x 128 cols per block)
//   [1600, 1840)  dec projection  (4 rows x 128 cols per block)
// 128 threads per block.
// ---------------------------------------------------------------------------
__device__ __forceinline__ void proj_part(
    const float* __restrict__ x, const float* __restrict__ w,
    const float* __restrict__ bias, __half* __restrict__ outp,
    int rb, int cb, int tid)
{
    __shared__ float xs[4][D_];
    const int r0 = rb * 4;
    const int j  = cb * 128 + (tid & 31) * 4;
    const int rw = tid >> 5;                 // warp -> row

    // load 4 rows of x (contiguous): 512 float4, 128 threads -> 4 each
    for (int i = tid; i < 4 * D_ / 4; i += 128)
        ((float4*)xs)[i] = ((const float4*)x)[(size_t)r0 * (D_ / 4) + i];
    __syncthreads();

    float4 acc = make_float4(0.f, 0.f, 0.f, 0.f);
#pragma unroll 8
    for (int k = 0; k < D_; ++k) {
        float4 wv = *(const float4*)&w[(size_t)k * J_ + j];
        float xv = xs[rw][k];
        acc.x += xv * wv.x; acc.y += xv * wv.y;
        acc.z += xv * wv.z; acc.w += xv * wv.w;
    }
    float4 bb = *(const float4*)&bias[j];
    uint2 o;
    o.x = pack_h2(acc.x + bb.x, acc.y + bb.y);
    o.y = pack_h2(acc.z + bb.z, acc.w + bb.w);
    *(uint2*)&outp[(size_t)(r0 + rw) * J_ + j] = o;
}

__global__ __launch_bounds__(128) void prep_kernel(
    const float* __restrict__ enc, const float* __restrict__ dec,
    const float* __restrict__ w_audio, const float* __restrict__ b_audio,
    const float* __restrict__ w_text,  const float* __restrict__ b_text,
    const float* __restrict__ wj)
{
    const int bid = blockIdx.x;
    const int tid = threadIdx.x;

    if (bid < NB_WPACK) {
        // ---- w transpose: tile (c0, j0) ----
        __shared__ float t[32][33];
        const int c0 = (bid & 31) * 32;        // C/32 = 32 tiles
        const int j0 = (bid >> 5) * 32;        // J/32 = 20 tiles
        const int tx = tid & 31, ty = tid >> 5;   // ty 0..3
#pragma unroll
        for (int i = 0; i < 8; ++i)
            t[ty + i * 4][tx] = wj[(size_t)(j0 + ty + i * 4) * C_ + c0 + tx];
        __syncthreads();
#pragma unroll
        for (int i = 0; i < 8; ++i)
            g_wh[(size_t)(c0 + ty + i * 4) * J_ + j0 + tx] =
                __float2half(t[tx][ty + i * 4]);
    } else if (bid < NB_WPACK + NB_ENC) {
        const int pb = bid - NB_WPACK;
        proj_part(enc, w_audio, b_audio, g_ah, pb / 5, pb % 5, tid);
    } else {
        const int pb = bid - NB_WPACK - NB_ENC;
        proj_part(dec, w_text, b_text, g_th, pb / 5, pb % 5, tid);
    }
}

// ---------------------------------------------------------------------------
// Fused join GEMM, fp16 mma m16n8k16 + ldmatrix, BK=64. (unchanged from R9)
// ---------------------------------------------------------------------------
__global__ __launch_bounds__(THREADS, 1) void join_kernel(
    const float* __restrict__ bj, float* __restrict__ out)
{
    extern __shared__ char sm[];
    const uint32_t sb = smem_u32(sm);
    const int tid  = threadIdx.x;
    const int wid  = tid >> 5;
    const int lane = tid & 31;
    const int col0 = blockIdx.x * BN;
    const int row0 = blockIdx.y * BM;

    int* aoffS = (int*)(sm + SM_AOFF);
    int* toffS = (int*)(sm + SM_TOFF);
    if (tid < BM) {
        int gr  = row0 + tid;
        int b   = gr / MN_;
        int rem = gr - b * MN_;
        int m   = rem / N_;
        int n   = rem - m * N_;
        aoffS[tid] = (b * M_ + m) * J_;
        toffS[tid] = (b * N_ + n) * J_;
    }
    __syncthreads();

    const int hrow = tid >> 2;
    const int kq   = tid & 3;
    const int aoff = aoffS[hrow] + kq * 16;
    const int toff = toffS[hrow] + kq * 16;

    const int wm = wid & 3;
    const int wn = wid >> 2;
    const int g  = lane >> 2;
    const int c  = lane & 3;

    const int l7 = lane & 7;
    const int lm = lane >> 3;
    const uint32_t a_loc = (uint32_t)((wm * 32 + (lm & 1) * 8 + l7) * ROWB + (lm >> 1) * 16);
    const uint32_t b_loc = (uint32_t)((wn * 64 + (lm >> 1) * 8 + l7) * ROWB + (lm & 1) * 16);

    float acc[2][8][4];
#pragma unroll
    for (int mi = 0; mi < 2; ++mi)
#pragma unroll
        for (int ni = 0; ni < 8; ++ni)
#pragma unroll
            for (int q = 0; q < 4; ++q) acc[mi][ni][q] = 0.f;

    // ---------------- prologue: tile 0 ----------------
    {
        uint4 va0 = *(const uint4*)(g_ah + aoff);
        uint4 va1 = *(const uint4*)(g_ah + aoff + 8);
        uint4 vt0 = *(const uint4*)(g_th + toff);
        uint4 vt1 = *(const uint4*)(g_th + toff + 8);

        uint32_t wbase = sb + SM_WS;
#pragma unroll
        for (int p = 0; p < 4; ++p) {
            int cid = tid + p * THREADS;
            int cc  = cid >> 3;
            int kk  = cid & 7;
            cp_async16(wbase + cc * ROWB + kk * 16,
                       (const char*)g_wh + (size_t)(col0 + cc) * J_ * 2 + kk * 16);
        }
        CP_COMMIT();

        char* hd = sm + SM_HS + hrow * ROWB + kq * 32;
        *(uint4*)(hd)      = h_combine(va0, vt0);
        *(uint4*)(hd + 16) = h_combine(va1, vt1);

        CP_WAIT0();
        __syncthreads();
    }

    // ---------------- main loop ----------------
    for (int kt = 0; kt < NKT; ++kt) {
        const int buf = kt & 1;
        const int nb  = buf ^ 1;
        const uint32_t ha = sb + SM_HS + buf * HS_B + a_loc;
        const uint32_t hb = sb + SM_WS + buf * WS_B + b_loc;

        uint4 va0, va1, vt0, vt1;
        if (kt < NKT - 1) {
            const int k0n = (kt + 1) * BK;
            va0 = *(const uint4*)(g_ah + aoff + k0n);
            va1 = *(const uint4*)(g_ah + aoff + k0n + 8);
            vt0 = *(const uint4*)(g_th + toff + k0n);
            vt1 = *(const uint4*)(g_th + toff + k0n + 8);

            uint32_t wbase = sb + SM_WS + nb * WS_B;
            const size_t ksrc = (size_t)(kt + 1) * BK * 2;
#pragma unroll
            for (int p = 0; p < 4; ++p) {
                int cid = tid + p * THREADS;
                int cc  = cid >> 3;
                int kk  = cid & 7;
                cp_async16(wbase + cc * ROWB + kk * 16,
                           (const char*)g_wh + (size_t)(col0 + cc) * J_ * 2 + ksrc + kk * 16);
            }
            CP_COMMIT();
        }

#pragma unroll
        for (int ks = 0; ks < 4; ++ks) {
            unsigned af[2][4];
            ldm_x4(af[0], ha + ks * 32);
            ldm_x4(af[1], ha + 16 * ROWB + ks * 32);
            unsigned bf[4][4];
#pragma unroll
            for (int p = 0; p < 4; ++p)
                ldm_x4(bf[p], hb + p * (16 * ROWB) + ks * 32);
#pragma unroll
            for (int p = 0; p < 4; ++p) {
#pragma unroll
                for (int mi = 0; mi < 2; ++mi) {
                    mma_f16(acc[mi][2 * p],
                            af[mi][0], af[mi][1], af[mi][2], af[mi][3],
                            bf[p][0], bf[p][1]);
                    mma_f16(acc[mi][2 * p + 1],
                            af[mi][0], af[mi][1], af[mi][2], af[mi][3],
                            bf[p][2], bf[p][3]);
                }
            }
        }

        if (kt < NKT - 1) {
            char* hd = sm + SM_HS + nb * HS_B + hrow * ROWB + kq * 32;
            *(uint4*)(hd)      = h_combine(va0, vt0);
            *(uint4*)(hd + 16) = h_combine(va1, vt1);
            CP_WAIT0();
        }
        __syncthreads();
    }

    // ---------------- epilogue: + b_join, fp32 stores ----------------
#pragma unroll
    for (int ni = 0; ni < 8; ++ni) {
        int gcol = col0 + wn * 64 + ni * 8 + c * 2;
        float2 bb = *(const float2*)(bj + gcol);
#pragma unroll
        for (int mi = 0; mi < 2; ++mi) {
            int grow = row0 + wm * 32 + mi * 16 + g;
            float2 v0 = make_float2(acc[mi][ni][0] + bb.x, acc[mi][ni][1] + bb.y);
            float2 v1 = make_float2(acc[mi][ni][2] + bb.x, acc[mi][ni][3] + bb.y);
            *(float2*)(out + (size_t)grow * C_ + gcol)       = v0;
            *(float2*)(out + (size_t)(grow + 8) * C_ + gcol) = v1;
        }
    }
}

// ---------------------------------------------------------------------------
// launch
// ---------------------------------------------------------------------------
extern "C" void kernel_launch(void* const* d_in, const int* in_sizes, int n_in,
                              void* d_out, int out_size)
{
    const float* enc     = (const float*)d_in[0];
    const float* dec     = (const float*)d_in[1];
    const float* w_audio = (const float*)d_in[2];
    const float* b_audio = (const float*)d_in[3];
    const float* w_text  = (const float*)d_in[4];
    const float* b_text  = (const float*)d_in[5];
    const float* w_join  = (const float*)d_in[6];
    const float* b_join  = (const float*)d_in[7];
    float* out = (float*)d_out;

    static int smem_set = 0;
    if (!smem_set) {
        cudaFuncSetAttribute(join_kernel, cudaFuncAttributeMaxDynamicSharedMemorySize,
                             SMEM_TOTAL);
        smem_set = 1;
    }

    prep_kernel<<<NB_PREP, 128>>>(enc, dec, w_audio, b_audio, w_text, b_text, w_join);
    join_kernel<<<dim3(C_ / BN, RTOT_ / BM), THREADS, SMEM_TOTAL>>>(b_join, out);
}

// round 11
// speedup vs baseline: 2.4869x; 1.1244x over previous
#include <cuda_runtime.h>
#include <cuda_fp16.h>
#include <cstdint>
#include <cstddef>

// Problem dims
#define B_ 2
#define M_ 384
#define N_ 96
#define D_ 512
#define J_ 640
#define C_ 1024
#define MN_ (M_*N_)        // 36864
#define RTOT_ (B_*MN_)     // 73728

// Join tiling: BM=64 x BN=256 x BK=64, 256 threads, 8 warps (2m x 4n), warp 32x64
// 2 CTAs/SM for phase-interleaved overlap of smem and tensor pipes.
#define BM 64
#define BN 256
#define BK 64
#define NKT (J_/BK)        // 10
#define THREADS 256

// fp16 row-major tiles, 144B row stride (banks 4r mod 32 -> ldmatrix/STS conflict-free)
#define ROWB 144
#define HS_B (BM*ROWB)     // 9216
#define WS_B (BN*ROWB)     // 36864

#define SM_AOFF  0
#define SM_TOFF  256
#define SM_HS    1024
#define SM_WS    (SM_HS + 2*HS_B)      // 19456
#define SMEM_TOTAL (SM_WS + 2*WS_B)    // 93184  (x2 CTAs = 186.4KB/SM)

// prep grid split
#define NB_WPACK ((C_/32)*(J_/32))       // 640
#define NB_ENC   ((B_*M_/16)*(J_/128))   // 48*5 = 240
#define NB_DEC   ((B_*N_/16)*(J_/128))   // 12*5 = 60
#define NB_PREP  (NB_WPACK + NB_ENC + NB_DEC)  // 940

// Scratch (device globals)
__device__ __half g_ah[B_*M_*J_];        // audio proj + bias, fp16
__device__ __half g_th[B_*N_*J_];        // text proj + bias, fp16
__device__ __half g_wh[(size_t)C_*J_];   // w_join transposed [col][j], fp16

// ---------------------------------------------------------------------------
// helpers
// ---------------------------------------------------------------------------
__device__ __forceinline__ uint32_t smem_u32(const void* p) {
    uint32_t a;
    asm("{ .reg .u64 t; cvta.to.shared.u64 t, %1; cvt.u32.u64 %0, t; }"
        : "=r"(a) : "l"(p));
    return a;
}
__device__ __forceinline__ float fast_tanh(float x) {
    float r;
    asm("tanh.approx.f32 %0, %1;" : "=f"(r) : "f"(x));
    return r;
}
__device__ __forceinline__ unsigned pack_h2(float lo, float hi) {
    unsigned r;
    asm("cvt.rn.f16x2.f32 %0, %2, %1;" : "=r"(r) : "f"(lo), "f"(hi));
    return r;
}
__device__ __forceinline__ void mma_f16(float d[4],
                                        unsigned a0, unsigned a1, unsigned a2, unsigned a3,
                                        unsigned b0, unsigned b1) {
    asm volatile(
        "mma.sync.aligned.m16n8k16.row.col.f32.f16.f16.f32 "
        "{%0,%1,%2,%3}, {%4,%5,%6,%7}, {%8,%9}, {%0,%1,%2,%3};"
        : "+f"(d[0]), "+f"(d[1]), "+f"(d[2]), "+f"(d[3])
        : "r"(a0), "r"(a1), "r"(a2), "r"(a3), "r"(b0), "r"(b1));
}
__device__ __forceinline__ void ldm_x4(unsigned r[4], uint32_t addr) {
    asm volatile("ldmatrix.sync.aligned.m8n8.x4.shared.b16 {%0,%1,%2,%3}, [%4];"
        : "=r"(r[0]), "=r"(r[1]), "=r"(r[2]), "=r"(r[3]) : "r"(addr));
}
__device__ __forceinline__ void cp_async16(uint32_t dst, const void* src) {
    asm volatile("cp.async.ca.shared.global [%0], [%1], 16;" :: "r"(dst), "l"(src));
}
#define CP_COMMIT() asm volatile("cp.async.commit_group;" ::: "memory")
#define CP_WAIT0()  asm volatile("cp.async.wait_group 0;" ::: "memory")

// combine 4 half2 (a) + 4 half2 (t) -> tanh -> packed uint4
__device__ __forceinline__ uint4 h_combine(uint4 a, uint4 t) {
    uint4 q;
    unsigned* av = (unsigned*)&a;
    unsigned* tv = (unsigned*)&t;
    unsigned* qv = (unsigned*)&q;
#pragma unroll
    for (int i = 0; i < 4; ++i) {
        float2 af = __half22float2(*(__half2*)&av[i]);
        float2 tf = __half22float2(*(__half2*)&tv[i]);
        qv[i] = pack_h2(fast_tanh(af.x + tf.x), fast_tanh(af.y + tf.y));
    }
    return q;
}

// ---------------------------------------------------------------------------
// Fused prep kernel: one launch does
//   [0, 640)    w_join [J,C] -> g_wh [C,J] fp16 transpose (32x32 tiles)
//   [640, 880)  enc projection  (16 rows x 128 cols per block)
//   [880, 940)  dec projection  (16 rows x 128 cols per block)
// 128 threads per block.
// ---------------------------------------------------------------------------
__device__ __forceinline__ void proj_part(
    const float* __restrict__ x, const float* __restrict__ w,
    const float* __restrict__ bias, __half* __restrict__ outp,
    int rb, int cb, int tid)
{
    __shared__ float xs[16][D_];
    const int r0 = rb * 16;
    const int j  = cb * 128 + (tid & 31) * 4;
    const int rw = tid >> 5;                  // 0..3; rows rw, rw+4, rw+8, rw+12

    // load 16 rows of x (contiguous): 2048 float4, 128 threads -> 16 each
    for (int i = tid; i < 16 * D_ / 4; i += 128)
        ((float4*)xs)[i] = ((const float4*)x)[(size_t)r0 * (D_ / 4) + i];
    __syncthreads();

    float4 acc[4];
#pragma unroll
    for (int r = 0; r < 4; ++r) acc[r] = make_float4(0.f, 0.f, 0.f, 0.f);

#pragma unroll 4
    for (int k = 0; k < D_; ++k) {
        float4 wv = *(const float4*)&w[(size_t)k * J_ + j];
#pragma unroll
        for (int r = 0; r < 4; ++r) {
            float xv = xs[rw + r * 4][k];
            acc[r].x += xv * wv.x; acc[r].y += xv * wv.y;
            acc[r].z += xv * wv.z; acc[r].w += xv * wv.w;
        }
    }
    float4 bb = *(const float4*)&bias[j];
#pragma unroll
    for (int r = 0; r < 4; ++r) {
        uint2 o;
        o.x = pack_h2(acc[r].x + bb.x, acc[r].y + bb.y);
        o.y = pack_h2(acc[r].z + bb.z, acc[r].w + bb.w);
        *(uint2*)&outp[(size_t)(r0 + rw + r * 4) * J_ + j] = o;
    }
}

__global__ __launch_bounds__(128) void prep_kernel(
    const float* __restrict__ enc, const float* __restrict__ dec,
    const float* __restrict__ w_audio, const float* __restrict__ b_audio,
    const float* __restrict__ w_text,  const float* __restrict__ b_text,
    const float* __restrict__ wj)
{
    const int bid = blockIdx.x;
    const int tid = threadIdx.x;

    if (bid < NB_WPACK) {
        __shared__ float t[32][33];
        const int c0 = (bid & 31) * 32;
        const int j0 = (bid >> 5) * 32;
        const int tx = tid & 31, ty = tid >> 5;   // ty 0..3
#pragma unroll
        for (int i = 0; i < 8; ++i)
            t[ty + i * 4][tx] = wj[(size_t)(j0 + ty + i * 4) * C_ + c0 + tx];
        __syncthreads();
#pragma unroll
        for (int i = 0; i < 8; ++i)
            g_wh[(size_t)(c0 + ty + i * 4) * J_ + j0 + tx] =
                __float2half(t[tx][ty + i * 4]);
    } else if (bid < NB_WPACK + NB_ENC) {
        const int pb = bid - NB_WPACK;
        proj_part(enc, w_audio, b_audio, g_ah, pb / 5, pb % 5, tid);
    } else {
        const int pb = bid - NB_WPACK - NB_ENC;
        proj_part(dec, w_text, b_text, g_th, pb / 5, pb % 5, tid);
    }
}

// ---------------------------------------------------------------------------
// Fused join GEMM, fp16 mma m16n8k16 + ldmatrix, BK=64, 2 CTAs/SM.
// ---------------------------------------------------------------------------
__global__ __launch_bounds__(THREADS, 2) void join_kernel(
    const float* __restrict__ bj, float* __restrict__ out)
{
    extern __shared__ char sm[];
    const uint32_t sb = smem_u32(sm);
    const int tid  = threadIdx.x;
    const int wid  = tid >> 5;
    const int lane = tid & 31;
    const int col0 = blockIdx.x * BN;
    const int row0 = blockIdx.y * BM;

    int* aoffS = (int*)(sm + SM_AOFF);
    int* toffS = (int*)(sm + SM_TOFF);
    if (tid < BM) {
        int gr  = row0 + tid;
        int b   = gr / MN_;
        int rem = gr - b * MN_;
        int m   = rem / N_;
        int n   = rem - m * N_;
        aoffS[tid] = (b * M_ + m) * J_;
        toffS[tid] = (b * N_ + n) * J_;
    }
    __syncthreads();

    // fill mapping: 4 threads per row (BM=64), each a 16-k chunk
    const int hrow = tid >> 2;              // 0..63
    const int kq   = tid & 3;               // k chunk = kq*16
    const int aoff = aoffS[hrow] + kq * 16;
    const int toff = toffS[hrow] + kq * 16;

    // warp compute mapping: 2m x 4n
    const int wm = wid & 1;
    const int wn = wid >> 1;
    const int g  = lane >> 2;
    const int c  = lane & 3;

    const int l7 = lane & 7;
    const int lm = lane >> 3;
    const uint32_t a_loc = (uint32_t)((wm * 32 + (lm & 1) * 8 + l7) * ROWB + (lm >> 1) * 16);
    const uint32_t b_loc = (uint32_t)((wn * 64 + (lm >> 1) * 8 + l7) * ROWB + (lm & 1) * 16);

    float acc[2][8][4];
#pragma unroll
    for (int mi = 0; mi < 2; ++mi)
#pragma unroll
        for (int ni = 0; ni < 8; ++ni)
#pragma unroll
            for (int q = 0; q < 4; ++q) acc[mi][ni][q] = 0.f;

    // ---------------- prologue: tile 0 ----------------
    {
        uint4 va0 = *(const uint4*)(g_ah + aoff);
        uint4 va1 = *(const uint4*)(g_ah + aoff + 8);
        uint4 vt0 = *(const uint4*)(g_th + toff);
        uint4 vt1 = *(const uint4*)(g_th + toff + 8);

        uint32_t wbase = sb + SM_WS;
#pragma unroll
        for (int p = 0; p < 8; ++p) {
            int cid = tid + p * THREADS;         // 0..2047
            int cc  = cid >> 3;                  // col 0..255
            int kk  = cid & 7;                   // 16B chunk
            cp_async16(wbase + cc * ROWB + kk * 16,
                       (const char*)g_wh + (size_t)(col0 + cc) * J_ * 2 + kk * 16);
        }
        CP_COMMIT();

        char* hd = sm + SM_HS + hrow * ROWB + kq * 32;
        *(uint4*)(hd)      = h_combine(va0, vt0);
        *(uint4*)(hd + 16) = h_combine(va1, vt1);

        CP_WAIT0();
        __syncthreads();
    }

    // ---------------- main loop ----------------
    for (int kt = 0; kt < NKT; ++kt) {
        const int buf = kt & 1;
        const int nb  = buf ^ 1;
        const uint32_t ha = sb + SM_HS + buf * HS_B + a_loc;
        const uint32_t hb = sb + SM_WS + buf * WS_B + b_loc;

        uint4 va0, va1, vt0, vt1;
        if (kt < NKT - 1) {
            const int k0n = (kt + 1) * BK;
            va0 = *(const uint4*)(g_ah + aoff + k0n);
            va1 = *(const uint4*)(g_ah + aoff + k0n + 8);
            vt0 = *(const uint4*)(g_th + toff + k0n);
            vt1 = *(const uint4*)(g_th + toff + k0n + 8);

            uint32_t wbase = sb + SM_WS + nb * WS_B;
            const size_t ksrc = (size_t)(kt + 1) * BK * 2;   // byte offset in w row
#pragma unroll
            for (int p = 0; p < 8; ++p) {
                int cid = tid + p * THREADS;
                int cc  = cid >> 3;
                int kk  = cid & 7;
                cp_async16(wbase + cc * ROWB + kk * 16,
                           (const char*)g_wh + (size_t)(col0 + cc) * J_ * 2 + ksrc + kk * 16);
            }
            CP_COMMIT();
        }

        // compute: 4 k-steps of K=16
#pragma unroll
        for (int ks = 0; ks < 4; ++ks) {
            unsigned af[2][4];
            ldm_x4(af[0], ha + ks * 32);
            ldm_x4(af[1], ha + 16 * ROWB + ks * 32);
            unsigned bf[4][4];
#pragma unroll
            for (int p = 0; p < 4; ++p)
                ldm_x4(bf[p], hb + p * (16 * ROWB) + ks * 32);
#pragma unroll
            for (int p = 0; p < 4; ++p) {
#pragma unroll
                for (int mi = 0; mi < 2; ++mi) {
                    mma_f16(acc[mi][2 * p],
                            af[mi][0], af[mi][1], af[mi][2], af[mi][3],
                            bf[p][0], bf[p][1]);
                    mma_f16(acc[mi][2 * p + 1],
                            af[mi][0], af[mi][1], af[mi][2], af[mi][3],
                            bf[p][2], bf[p][3]);
                }
            }
        }

        // finish next h tile
        if (kt < NKT - 1) {
            char* hd = sm + SM_HS + nb * HS_B + hrow * ROWB + kq * 32;
            *(uint4*)(hd)      = h_combine(va0, vt0);
            *(uint4*)(hd + 16) = h_combine(va1, vt1);
            CP_WAIT0();
        }
        __syncthreads();
    }

    // ---------------- epilogue: + b_join, fp32 stores ----------------
#pragma unroll
    for (int ni = 0; ni < 8; ++ni) {
        int gcol = col0 + wn * 64 + ni * 8 + c * 2;
        float2 bb = *(const float2*)(bj + gcol);
#pragma unroll
        for (int mi = 0; mi < 2; ++mi) {
            int grow = row0 + wm * 32 + mi * 16 + g;
            float2 v0 = make_float2(acc[mi][ni][0] + bb.x, acc[mi][ni][1] + bb.y);
            float2 v1 = make_float2(acc[mi][ni][2] + bb.x, acc[mi][ni][3] + bb.y);
            *(float2*)(out + (size_t)grow * C_ + gcol)       = v0;
            *(float2*)(out + (size_t)(grow + 8) * C_ + gcol) = v1;
        }
    }
}

// ---------------------------------------------------------------------------
// launch
// ---------------------------------------------------------------------------
extern "C" void kernel_launch(void* const* d_in, const int* in_sizes, int n_in,
                              void* d_out, int out_size)
{
    const float* enc     = (const float*)d_in[0];
    const float* dec     = (const float*)d_in[1];
    const float* w_audio = (const float*)d_in[2];
    const float* b_audio = (const float*)d_in[3];
    const float* w_text  = (const float*)d_in[4];
    const float* b_text  = (const float*)d_in[5];
    const float* w_join  = (const float*)d_in[6];
    const float* b_join  = (const float*)d_in[7];
    float* out = (float*)d_out;

    static int smem_set = 0;
    if (!smem_set) {
        cudaFuncSetAttribute(join_kernel, cudaFuncAttributeMaxDynamicSharedMemorySize,
                             SMEM_TOTAL);
        smem_set = 1;
    }

    prep_kernel<<<NB_PREP, 128>>>(enc, dec, w_audio, b_audio, w_text, b_text, w_join);
    join_kernel<<<dim3(C_ / BN, RTOT_ / BM), THREADS, SMEM_TOTAL>>>(b_join, out);
}